// round 1
// baseline (speedup 1.0000x reference)
#include <cuda_runtime.h>
#include <cstdint>

// HalftoneMARLLoss — analytic single-flip formulation.
//
// Key identities vs the reference:
//  * h' differs from h at one pixel a by delta in {-1,0,+1}; conv is linear:
//      mu_h'(p)   = mu_h(p)   + delta * K[p-a]
//      conv(h'c)  = conv(hc)  + delta * c[a] * K[p-a]
//      conv(h'^2) = conv(h')               (h' is exactly {0,1} in fp32)
//  * c-side maps (mu_c, sig_c, c_contrast) are candidate-independent.
//  * Per-pixel reward term changes only inside the 11x11 kernel footprint of a.
//  * loss = -( S_0 + S_1 + (sum_flips pi*dT)/1024 ) / 2048,
//    S_b = sum_p T0(p),  dT = sum_window (U_new - U_base),
//    U(p) = WS*c_contrast*ssim - (mu_h-mu_c)^2   (the c_contrast-only part of T
//    cancels in dT).
//
// RNG: JAX threefry2x32, key(42) = (0,42). Modern JAX defaults to
// threefry_partitionable=True: per element e, bits = x0^x1 of TF(hi=0, lo=e).
// Legacy (pre-0.5) pairing mode kept behind the macro below.
#define THREEFRY_PARTITIONABLE 1

#define HW 1024
#define WS_F 0.06f
#define C1_F 1e-4f   // (0.01*1)^2
#define C2_F 9e-4f   // (0.03*1)^2
#define EPS_F 1e-12f

// scratch (static device globals — no allocations)
__device__ float g_muh[2 * HW], g_muc[2 * HW], g_hc[2 * HW];
__device__ float g_sigc[2 * HW], g_wsc[2 * HW], g_U0[2 * HW];
__device__ float g_h[2 * HW];
__device__ float g_S[2];
__device__ float g_part[128];

__device__ __forceinline__ void tf_round(uint32_t& x0, uint32_t& x1, int r) {
    x0 += x1;
    x1 = (x1 << r) | (x1 >> (32 - r));
    x1 ^= x0;
}

__device__ __forceinline__ void threefry2x32(uint32_t k0, uint32_t k1,
                                             uint32_t& x0, uint32_t& x1) {
    uint32_t ks2 = k0 ^ k1 ^ 0x1BD11BDAu;
    x0 += k0; x1 += k1;
    tf_round(x0, x1, 13); tf_round(x0, x1, 15); tf_round(x0, x1, 26); tf_round(x0, x1, 6);
    x0 += k1; x1 += ks2 + 1u;
    tf_round(x0, x1, 17); tf_round(x0, x1, 29); tf_round(x0, x1, 16); tf_round(x0, x1, 24);
    x0 += ks2; x1 += k0 + 2u;
    tf_round(x0, x1, 13); tf_round(x0, x1, 15); tf_round(x0, x1, 26); tf_round(x0, x1, 6);
    x0 += k0; x1 += k1 + 3u;
    tf_round(x0, x1, 17); tf_round(x0, x1, 29); tf_round(x0, x1, 16); tf_round(x0, x1, 24);
    x0 += k1; x1 += ks2 + 4u;
    tf_round(x0, x1, 13); tf_round(x0, x1, 15); tf_round(x0, x1, 26); tf_round(x0, x1, 6);
    x0 += ks2; x1 += k0 + 5u;
}

__device__ __forceinline__ float jax_uniform_elem(int e) {
#if THREEFRY_PARTITIONABLE
    uint32_t x0 = 0u, x1 = (uint32_t)e;
    threefry2x32(0u, 42u, x0, x1);
    uint32_t bits = x0 ^ x1;
#else
    // legacy: counts iota(2048) split into halves; pair (e&1023, (e&1023)+1024)
    uint32_t x0 = (uint32_t)(e & (HW - 1));
    uint32_t x1 = x0 + (uint32_t)HW;
    threefry2x32(0u, 42u, x0, x1);
    uint32_t bits = (e < HW) ? x0 : x1;
#endif
    float f = __uint_as_float((bits >> 9) | 0x3f800000u) - 1.0f;
    return fmaxf(f, 0.0f);
}

__device__ __forceinline__ void gauss_norm(float* g) {
    float s = 0.f;
#pragma unroll
    for (int i = 0; i < 11; i++) {
        float d = (float)(i - 5);
        g[i] = expf(-0.125f * d * d);  // 0.5/sigma^2 = 0.125, sigma=2
        s += g[i];
    }
    float inv = 1.0f / s;
#pragma unroll
    for (int i = 0; i < 11; i++) g[i] *= inv;
}

// Kernel 1: per-batch base maps + base reward sum. grid=(2), block=(1024)
__global__ __launch_bounds__(1024) void k_base(const float* __restrict__ prob,
                                               const float* __restrict__ cin) {
    const int b = blockIdx.x;
    const int p = threadIdx.x;
    const int y = p >> 5, x = p & 31;

    __shared__ float A0[HW], A1[HW], A2[HW], A3[HW];
    __shared__ float T0s[HW], T1s[HW], T2s[HW], T3s[HW];
    __shared__ float red[32];

    float g[11];
    gauss_norm(g);

    const int e = b * HW + p;
    float h = (jax_uniform_elem(e) < prob[e]) ? 1.f : 0.f;
    float cv = cin[e];
    g_h[e] = h;

    A0[p] = h; A1[p] = cv; A2[p] = h * cv; A3[p] = cv * cv;
    __syncthreads();

    // horizontal pass (zero SAME padding)
    float a0 = 0.f, a1 = 0.f, a2 = 0.f, a3 = 0.f;
#pragma unroll
    for (int dx = -5; dx <= 5; dx++) {
        int xx = x + dx;
        if ((unsigned)xx < 32u) {
            float w = g[dx + 5];
            int q = (y << 5) | xx;
            a0 += w * A0[q]; a1 += w * A1[q];
            a2 += w * A2[q]; a3 += w * A3[q];
        }
    }
    T0s[p] = a0; T1s[p] = a1; T2s[p] = a2; T3s[p] = a3;
    __syncthreads();

    // vertical pass
    float muh = 0.f, muc = 0.f, hcv = 0.f, c2v = 0.f;
#pragma unroll
    for (int dy = -5; dy <= 5; dy++) {
        int yy = y + dy;
        if ((unsigned)yy < 32u) {
            float w = g[dy + 5];
            int q = (yy << 5) | x;
            muh += w * T0s[q]; muc += w * T1s[q];
            hcv += w * T2s[q]; c2v += w * T3s[q];
        }
    }
    __syncthreads();

    // c_var = conv((c - mu_c)^2)
    float dcm = cv - muc;
    A0[p] = dcm * dcm;
    __syncthreads();
    float af = 0.f;
#pragma unroll
    for (int dx = -5; dx <= 5; dx++) {
        int xx = x + dx;
        if ((unsigned)xx < 32u) af += g[dx + 5] * A0[(y << 5) | xx];
    }
    T0s[p] = af;
    __syncthreads();
    float cvar = 0.f;
#pragma unroll
    for (int dy = -5; dy <= 5; dy++) {
        int yy = y + dy;
        if ((unsigned)yy < 32u) cvar += g[dy + 5] * T0s[(yy << 5) | x];
    }

    // base per-pixel reward term
    float sigh = muh - muh * muh;          // conv(h^2) == conv(h), h binary
    float sigc = c2v - muc * muc;
    float sighc = hcv - muh * muc;
    float sq = sqrtf(fmaxf(sigh * sigc, 0.f) + EPS_F);
    float num = (2.f * muh * muc + C1_F) * (2.f * sq + C2_F) * (2.f * sighc + C2_F);
    float den = (muh * muh + muc * muc + C1_F) * (sigh + sigc + C2_F) * (sq + C2_F + EPS_F);
    float ssim = num / den;
    float ccon = fminf(2.f * sqrtf(cvar + EPS_F), 1.f);
    float wsc = WS_F * ccon;
    float dmh = muh - muc;
    float U0 = wsc * ssim - dmh * dmh;
    float Tbase = U0 + WS_F - wsc;         // + WS*(1 - c_contrast)

    g_muh[e] = muh; g_muc[e] = muc; g_hc[e] = hcv;
    g_sigc[e] = sigc; g_wsc[e] = wsc; g_U0[e] = U0;

    // block reduce sum(Tbase) -> g_S[b]
    float v = Tbase;
#pragma unroll
    for (int o = 16; o; o >>= 1) v += __shfl_xor_sync(0xffffffffu, v, o);
    if ((p & 31) == 0) red[p >> 5] = v;
    __syncthreads();
    if (p < 32) {
        float w2 = red[p];
#pragma unroll
        for (int o = 16; o; o >>= 1) w2 += __shfl_xor_sync(0xffffffffu, w2, o);
        if (p == 0) g_S[b] = w2;
    }
}

// Kernel 2: one warp per flip candidate (2048 warps). grid=(128), block=(512)
__global__ __launch_bounds__(512) void k_flips(const float* __restrict__ prob,
                                               const float* __restrict__ cin) {
    const int lane = threadIdx.x & 31;
    const int warp = threadIdx.x >> 5;
    const int gw = (blockIdx.x << 4) + warp;   // 0..2047 == b*1024 + a
    const int b = gw >> 10;
    const int a = gw & (HW - 1);
    const int ay = a >> 5, ax = a & 31;

    float g[11];
    gauss_norm(g);

    float h = g_h[gw];
    float delta = 1.f - 2.f * h;               // flip to the other binary value
    float pa = prob[gw];
    float pi = (h == 0.f) ? pa : (1.f - pa);   // prob of the flip action
    float ca = cin[gw];
    float dca = delta * ca;

    float dacc = 0.f;
    for (int t = lane; t < 121; t += 32) {
        int row = t / 11;
        int col = t - row * 11;
        int yy = ay + row - 5, xx = ax + col - 5;
        if ((unsigned)yy < 32u && (unsigned)xx < 32u) {
            float w = g[row] * g[col];
            int q = (b << 10) + (yy << 5) + xx;
            float muc = g_muc[q];
            float muh = g_muh[q] + delta * w;
            float sigc = g_sigc[q];
            float sighc = g_hc[q] + dca * w - muh * muc;
            float sigh = muh - muh * muh;
            float sq = sqrtf(fmaxf(sigh * sigc, 0.f) + EPS_F);
            float num = (2.f * muh * muc + C1_F) * (2.f * sq + C2_F) * (2.f * sighc + C2_F);
            float den = (muh * muh + muc * muc + C1_F) * (sigh + sigc + C2_F) * (sq + C2_F + EPS_F);
            float dmh = muh - muc;
            float Un = g_wsc[q] * (num / den) - dmh * dmh;
            dacc += Un - g_U0[q];
        }
    }
#pragma unroll
    for (int o = 16; o; o >>= 1) dacc += __shfl_xor_sync(0xffffffffu, dacc, o);

    __shared__ float wsum[16];
    if (lane == 0) wsum[warp] = pi * dacc;
    __syncthreads();
    if (threadIdx.x == 0) {
        float s = 0.f;
#pragma unroll
        for (int i = 0; i < 16; i++) s += wsum[i];
        g_part[blockIdx.x] = s;   // deterministic: no atomics
    }
}

// Kernel 3: final deterministic reduce. grid=(1), block=(128)
__global__ __launch_bounds__(128) void k_final(float* __restrict__ out) {
    const int tid = threadIdx.x;
    __shared__ float sh[4];
    float v = g_part[tid];
#pragma unroll
    for (int o = 16; o; o >>= 1) v += __shfl_xor_sync(0xffffffffu, v, o);
    if ((tid & 31) == 0) sh[tid >> 5] = v;
    __syncthreads();
    if (tid == 0) {
        float A = sh[0] + sh[1] + sh[2] + sh[3];
        out[0] = -(g_S[0] + g_S[1] + A * (1.0f / 1024.0f)) * (1.0f / 2048.0f);
    }
}

extern "C" void kernel_launch(void* const* d_in, const int* in_sizes, int n_in,
                              void* d_out, int out_size) {
    const float* prob = (const float*)d_in[0];
    const float* c = (const float*)d_in[1];
    // d_in[2] (z) is unused by the reference.
    float* out = (float*)d_out;

    k_base<<<2, 1024>>>(prob, c);
    k_flips<<<128, 512>>>(prob, c);
    k_final<<<1, 128>>>(out);
}